// round 8
// baseline (speedup 1.0000x reference)
#include <cuda_runtime.h>
#include <cstdint>
#include <math_constants.h>

#define NN 50000
#define NE 800000
#define IND 512
#define HID 64
#define OUTD 40

#define NBC 782   // count blocks: NE/4/256 rounded up
#define NBG 391   // gemm1 blocks: NN/128 rounded up
#define NB  49    // scan blocks: NN/1024 rounded up

// ---------------- scratch (static device arrays; no allocation) -------------
__device__ float g_dis[NN];
__device__ int   g_cnt[NN];
__device__ int   g_cur[NN];
__device__ int   g_offs[NN + 1];
__device__ int   g_bsum[64];
__device__ int   g_csr[NE];                 // src ids grouped by dst
__device__ float g_hs1[(size_t)NN * HID];   // raw (x@W1)[i]  (dis applied in agg1)
__device__ float g_h[(size_t)NN * HID];     // post relu+dropout
__device__ float g_hs2[(size_t)NN * OUTD];  // d^-1/2[i] * (h@W2)[i]

// ---------------- GEMM1 helpers (TF32 tensor cores) --------------------------
__device__ __forceinline__ uint32_t f2tf32(float f) {
    uint32_t r;
    asm("cvt.rna.tf32.f32 %0, %1;" : "=r"(r) : "f"(f));
    return r;
}

__device__ __forceinline__ void mma_tf32(float* c, const uint32_t* a, const uint32_t* b) {
    asm volatile(
        "mma.sync.aligned.m16n8k8.row.col.f32.tf32.tf32.f32 "
        "{%0,%1,%2,%3}, {%4,%5,%6,%7}, {%8,%9}, {%0,%1,%2,%3};"
        : "+f"(c[0]), "+f"(c[1]), "+f"(c[2]), "+f"(c[3])
        : "r"(a[0]), "r"(a[1]), "r"(a[2]), "r"(a[3]), "r"(b[0]), "r"(b[1]));
}

#define XPAD 36
#define WPAD 72

// ---------------- fused: edge count (blocks < NBC)  ∥  GEMM1 (rest) ---------
__global__ __launch_bounds__(256) void k_count_gemm1(const int* __restrict__ dst,
                                                     const float* __restrict__ x,
                                                     const float* __restrict__ W1) {
    __shared__ uint32_t xs[128][XPAD];
    __shared__ uint32_t ws[32][WPAD];

    if (blockIdx.x < NBC) {   // ---- count path (independent of smem) ----
        int i = (blockIdx.x * 256 + threadIdx.x) * 4;
        if (i < NE) {
            int4 d = *(const int4*)(dst + i);
            atomicAdd(&g_cnt[d.x], 1);
            atomicAdd(&g_cnt[d.y], 1);
            atomicAdd(&g_cnt[d.z], 1);
            atomicAdd(&g_cnt[d.w], 1);
        }
        return;
    }

    // ---- GEMM1 path: hs1 = x @ W1 (raw, no dis) ----
    const int row0 = (blockIdx.x - NBC) * 128;
    const int t = threadIdx.x;
    const int wid = t >> 5, lane = t & 31;
    const int wm = wid >> 1, wn = wid & 1;
    const int g = lane >> 2, tig = lane & 3;

    float acc[2][4][4] = {};

    for (int kb = 0; kb < IND; kb += 32) {
#pragma unroll
        for (int i = 0; i < 4; i++) {
            int f = t + 256 * i;
            int r = f >> 3, q = (f & 7) << 2;
            int gr = row0 + r;
            float4 v = make_float4(0.f, 0.f, 0.f, 0.f);
            if (gr < NN) v = *(const float4*)(x + (size_t)gr * IND + kb + q);
            xs[r][q]     = f2tf32(v.x);
            xs[r][q + 1] = f2tf32(v.y);
            xs[r][q + 2] = f2tf32(v.z);
            xs[r][q + 3] = f2tf32(v.w);
        }
#pragma unroll
        for (int i = 0; i < 2; i++) {
            int f = t + 256 * i;
            int kk = f >> 4, c4 = (f & 15) << 2;
            float4 v = *(const float4*)(W1 + (size_t)(kb + kk) * HID + c4);
            ws[kk][c4]     = f2tf32(v.x);
            ws[kk][c4 + 1] = f2tf32(v.y);
            ws[kk][c4 + 2] = f2tf32(v.z);
            ws[kk][c4 + 3] = f2tf32(v.w);
        }
        __syncthreads();
#pragma unroll
        for (int k8 = 0; k8 < 4; k8++) {
            int k0 = k8 * 8;
            uint32_t a[2][4], b[4][2];
#pragma unroll
            for (int i = 0; i < 2; i++) {
                int rb = wm * 32 + i * 16;
                a[i][0] = xs[rb + g][k0 + tig];
                a[i][1] = xs[rb + g + 8][k0 + tig];
                a[i][2] = xs[rb + g][k0 + tig + 4];
                a[i][3] = xs[rb + g + 8][k0 + tig + 4];
            }
#pragma unroll
            for (int j = 0; j < 4; j++) {
                int nb = wn * 32 + j * 8 + g;
                b[j][0] = ws[k0 + tig][nb];
                b[j][1] = ws[k0 + tig + 4][nb];
            }
#pragma unroll
            for (int i = 0; i < 2; i++)
#pragma unroll
                for (int j = 0; j < 4; j++)
                    mma_tf32(acc[i][j], a[i], b[j]);
        }
        __syncthreads();
    }

#pragma unroll
    for (int i = 0; i < 2; i++) {
        int r_lo = row0 + wm * 32 + i * 16 + g;
        int r_hi = r_lo + 8;
#pragma unroll
        for (int j = 0; j < 4; j++) {
            int c = wn * 32 + j * 8 + 2 * tig;
            if (r_lo < NN)
                *(float2*)(g_hs1 + (size_t)r_lo * HID + c) =
                    make_float2(acc[i][j][0], acc[i][j][1]);
            if (r_hi < NN)
                *(float2*)(g_hs1 + (size_t)r_hi * HID + c) =
                    make_float2(acc[i][j][2], acc[i][j][3]);
        }
    }
}

// scan1: per-block (1024 nodes) sums
__global__ void k_scan1() {
    int t = threadIdx.x, lane = t & 31, w = t >> 5;
    int i = blockIdx.x * 1024 + t;
    int v = (i < NN) ? g_cnt[i] : 0;
#pragma unroll
    for (int o = 16; o; o >>= 1) v += __shfl_xor_sync(0xFFFFFFFFu, v, o);
    __shared__ int ws[32];
    if (lane == 0) ws[w] = v;
    __syncthreads();
    if (w == 0) {
        int y = ws[lane];
#pragma unroll
        for (int o = 16; o; o >>= 1) y += __shfl_xor_sync(0xFFFFFFFFu, y, o);
        if (lane == 0) g_bsum[blockIdx.x] = y;
    }
}

// scan3: per-block exclusive scan + inline cross-block base -> offs, cur, dis
__global__ void k_scan3() {
    __shared__ int wsum[32];
    __shared__ int s_base;
    int t = threadIdx.x, lane = t & 31, w = t >> 5;

    if (t == 0) {   // base = sum of prior block sums (L2-resident, overlapped)
        int b = 0;
#pragma unroll 8
        for (int j = 0; j < blockIdx.x; j++) b += g_bsum[j];
        s_base = b;
    }

    int i = blockIdx.x * 1024 + t;
    int v = (i < NN) ? g_cnt[i] : 0;
    int x = v;
#pragma unroll
    for (int o = 1; o < 32; o <<= 1) {
        int n = __shfl_up_sync(0xFFFFFFFFu, x, o);
        if (lane >= o) x += n;
    }
    if (lane == 31) wsum[w] = x;
    __syncthreads();
    if (w == 0) {
        int y = wsum[lane];
#pragma unroll
        for (int o = 1; o < 32; o <<= 1) {
            int n = __shfl_up_sync(0xFFFFFFFFu, y, o);
            if (lane >= o) y += n;
        }
        wsum[lane] = y;
    }
    __syncthreads();
    int excl = s_base + x - v + (w ? wsum[w - 1] : 0);
    if (i < NN) {
        g_offs[i] = excl;
        g_cur[i]  = excl;
        g_dis[i]  = rsqrtf((float)(v + 1));   // +1 self-loop
    }
    if (i == 0) g_offs[NN] = NE;
}

__global__ void k_fill(const int* __restrict__ src, const int* __restrict__ dst) {
    int i = (blockIdx.x * blockDim.x + threadIdx.x) * 4;
    if (i >= NE) return;
    int4 s4 = *(const int4*)(src + i);
    int4 d4 = *(const int4*)(dst + i);
    g_csr[atomicAdd(&g_cur[d4.x], 1)] = s4.x;
    g_csr[atomicAdd(&g_cur[d4.y], 1)] = s4.y;
    g_csr[atomicAdd(&g_cur[d4.z], 1)] = s4.z;
    g_csr[atomicAdd(&g_cur[d4.w], 1)] = s4.w;
}

// ---------------- threefry2x32 (JAX partitionable), key (0, 42) -------------
__device__ __forceinline__ uint32_t rotl32(uint32_t x, int r) {
    return (x << r) | (x >> (32 - r));
}

__device__ __forceinline__ uint32_t tf_bits(uint32_t i) {
    uint32_t x0 = 0u, x1 = i;
    const uint32_t k0 = 0u, k1 = 42u, k2 = 0x1BD11BDAu ^ 42u;
    x0 += k0; x1 += k1;
#define TF_ROUND(r) { x0 += x1; x1 = rotl32(x1, r); x1 ^= x0; }
    TF_ROUND(13) TF_ROUND(15) TF_ROUND(26) TF_ROUND(6)
    x0 += k1; x1 += k2 + 1u;
    TF_ROUND(17) TF_ROUND(29) TF_ROUND(16) TF_ROUND(24)
    x0 += k2; x1 += k0 + 2u;
    TF_ROUND(13) TF_ROUND(15) TF_ROUND(26) TF_ROUND(6)
    x0 += k0; x1 += k1 + 3u;
    TF_ROUND(17) TF_ROUND(29) TF_ROUND(16) TF_ROUND(24)
    x0 += k1; x1 += k2 + 4u;
    TF_ROUND(13) TF_ROUND(15) TF_ROUND(26) TF_ROUND(6)
    x0 += k2; x1 += k0 + 5u;
#undef TF_ROUND
    return x0 ^ x1;
}

// ---------------- agg1: warp/node, dis[src] applied at gather ---------------
__global__ void k_agg1(const float* __restrict__ b1) {
    int node = blockIdx.x * (blockDim.x >> 5) + (threadIdx.x >> 5);
    if (node >= NN) return;
    int lane = threadIdx.x & 31;
    int c4 = lane & 15, p = lane >> 4;
    const float4* hv = (const float4*)g_hs1;

    float4 acc = make_float4(0.f, 0.f, 0.f, 0.f);
    if (p == 0) {   // self-loop: dis[node] * ht[node]
        float dn = g_dis[node];
        float4 r = hv[(size_t)node * 16 + c4];
        acc.x = dn * r.x; acc.y = dn * r.y; acc.z = dn * r.z; acc.w = dn * r.w;
    }

    int beg = g_offs[node], end = g_offs[node + 1];
    int k = beg + p;
    for (; k + 2 < end; k += 4) {
        int s0 = __ldg(&g_csr[k]);
        int s1 = __ldg(&g_csr[k + 2]);
        float w0 = g_dis[s0];
        float w1 = g_dis[s1];
        float4 v0 = hv[(size_t)s0 * 16 + c4];
        float4 v1 = hv[(size_t)s1 * 16 + c4];
        acc.x = fmaf(w0, v0.x, acc.x); acc.y = fmaf(w0, v0.y, acc.y);
        acc.z = fmaf(w0, v0.z, acc.z); acc.w = fmaf(w0, v0.w, acc.w);
        acc.x = fmaf(w1, v1.x, acc.x); acc.y = fmaf(w1, v1.y, acc.y);
        acc.z = fmaf(w1, v1.z, acc.z); acc.w = fmaf(w1, v1.w, acc.w);
    }
    if (k < end) {
        int s = __ldg(&g_csr[k]);
        float w0 = g_dis[s];
        float4 v = hv[(size_t)s * 16 + c4];
        acc.x = fmaf(w0, v.x, acc.x); acc.y = fmaf(w0, v.y, acc.y);
        acc.z = fmaf(w0, v.z, acc.z); acc.w = fmaf(w0, v.w, acc.w);
    }

    acc.x += __shfl_down_sync(0xFFFFFFFFu, acc.x, 16);
    acc.y += __shfl_down_sync(0xFFFFFFFFu, acc.y, 16);
    acc.z += __shfl_down_sync(0xFFFFFFFFu, acc.z, 16);
    acc.w += __shfl_down_sync(0xFFFFFFFFu, acc.w, 16);

    if (p == 0) {
        float d = g_dis[node];
        float4 bb = ((const float4*)b1)[c4];
        float4 v;
        v.x = fmaxf(fmaf(d, acc.x, bb.x), 0.f);
        v.y = fmaxf(fmaf(d, acc.y, bb.y), 0.f);
        v.z = fmaxf(fmaf(d, acc.z, bb.z), 0.f);
        v.w = fmaxf(fmaf(d, acc.w, bb.w), 0.f);
        uint32_t i0 = (uint32_t)node * HID + c4 * 4;
        v.x = (tf_bits(i0)     < 0x80000000u) ? v.x * 2.0f : 0.f;
        v.y = (tf_bits(i0 + 1) < 0x80000000u) ? v.y * 2.0f : 0.f;
        v.z = (tf_bits(i0 + 2) < 0x80000000u) ? v.z * 2.0f : 0.f;
        v.w = (tf_bits(i0 + 3) < 0x80000000u) ? v.w * 2.0f : 0.f;
        ((float4*)g_h)[(size_t)node * 16 + c4] = v;
    }
}

// ---------------- GEMM2: hs2 = dis .* (h @ W2) ------------------------------
__global__ void k_gemm2(const float* __restrict__ W2) {
    __shared__ float hsm[64][65];
    __shared__ float w2s[64][OUTD];
    const int row0 = blockIdx.x * 64;
    const int t = threadIdx.x;

    for (int idx = t; idx < 64 * 64; idx += 320) {
        int r = idx >> 6, k = idx & 63;
        int gr = row0 + r;
        hsm[r][k] = (gr < NN) ? g_h[(size_t)gr * HID + k] : 0.f;
    }
    for (int idx = t; idx < 64 * OUTD; idx += 320)
        w2s[idx / OUTD][idx % OUTD] = W2[idx];
    __syncthreads();

    int r8 = t / OUTD;
    int c = t % OUTD;
    float acc[8] = {};
#pragma unroll
    for (int k = 0; k < 64; k++) {
        float b = w2s[k][c];
#pragma unroll
        for (int i = 0; i < 8; i++)
            acc[i] = fmaf(hsm[r8 * 8 + i][k], b, acc[i]);
    }
#pragma unroll
    for (int i = 0; i < 8; i++) {
        int row = row0 + r8 * 8 + i;
        if (row < NN)
            g_hs2[(size_t)row * OUTD + c] = g_dis[row] * acc[i];
    }
}

// ---------------- agg2: warp/node, 10 float4 chunks x 3 neighbor slots ------
__global__ void k_agg2(const float* __restrict__ b2, float* __restrict__ out) {
    int node = blockIdx.x * (blockDim.x >> 5) + (threadIdx.x >> 5);
    if (node >= NN) return;
    int lane = threadIdx.x & 31;
    int c = lane % 10;
    int p = (lane < 30) ? (lane / 10) : 3;     // slots 0..2; lanes 30,31 idle
    const float4* hv = (const float4*)g_hs2;   // row stride 10 float4

    float4 acc = make_float4(0.f, 0.f, 0.f, 0.f);
    if (lane < 10) acc = hv[(size_t)node * 10 + c];   // self-loop

    int beg = g_offs[node], end = g_offs[node + 1];
    if (p < 3) {
        int k = beg + p;
        for (; k + 3 < end; k += 6) {
            int s0 = __ldg(&g_csr[k]);
            int s1 = __ldg(&g_csr[k + 3]);
            float4 v0 = hv[(size_t)s0 * 10 + c];
            float4 v1 = hv[(size_t)s1 * 10 + c];
            acc.x += v0.x; acc.y += v0.y; acc.z += v0.z; acc.w += v0.w;
            acc.x += v1.x; acc.y += v1.y; acc.z += v1.z; acc.w += v1.w;
        }
        if (k < end) {
            int s = __ldg(&g_csr[k]);
            float4 v = hv[(size_t)s * 10 + c];
            acc.x += v.x; acc.y += v.y; acc.z += v.z; acc.w += v.w;
        }
    }

    float rx = acc.x + __shfl_down_sync(0xFFFFFFFFu, acc.x, 10) + __shfl_down_sync(0xFFFFFFFFu, acc.x, 20);
    float ry = acc.y + __shfl_down_sync(0xFFFFFFFFu, acc.y, 10) + __shfl_down_sync(0xFFFFFFFFu, acc.y, 20);
    float rz = acc.z + __shfl_down_sync(0xFFFFFFFFu, acc.z, 10) + __shfl_down_sync(0xFFFFFFFFu, acc.z, 20);
    float rw = acc.w + __shfl_down_sync(0xFFFFFFFFu, acc.w, 10) + __shfl_down_sync(0xFFFFFFFFu, acc.w, 20);

    float4 v = make_float4(-CUDART_INF_F, -CUDART_INF_F, -CUDART_INF_F, -CUDART_INF_F);
    if (lane < 10) {
        float d = g_dis[node];
        float4 bb = ((const float4*)b2)[c];
        v.x = fmaf(d, rx, bb.x);
        v.y = fmaf(d, ry, bb.y);
        v.z = fmaf(d, rz, bb.z);
        v.w = fmaf(d, rw, bb.w);
    }
    float m = fmaxf(fmaxf(v.x, v.y), fmaxf(v.z, v.w));
#pragma unroll
    for (int o = 16; o; o >>= 1) m = fmaxf(m, __shfl_xor_sync(0xFFFFFFFFu, m, o));
    float s = 0.f;
    if (lane < 10)
        s = expf(v.x - m) + expf(v.y - m) + expf(v.z - m) + expf(v.w - m);
#pragma unroll
    for (int o = 16; o; o >>= 1) s += __shfl_xor_sync(0xFFFFFFFFu, s, o);
    float lse = m + logf(s);

    if (lane < 10) {
        float4 o4 = make_float4(v.x - lse, v.y - lse, v.z - lse, v.w - lse);
        ((float4*)out)[(size_t)node * 10 + c] = o4;
    }
}

// ---------------- launch -----------------------------------------------------
extern "C" void kernel_launch(void* const* d_in, const int* in_sizes, int n_in,
                              void* d_out, int out_size) {
    const float* x  = (const float*)d_in[0];
    const int*   ei = (const int*)d_in[1];     // [2, NE] row-major
    const float* W1 = (const float*)d_in[2];
    const float* b1 = (const float*)d_in[3];
    const float* W2 = (const float*)d_in[4];
    const float* b2 = (const float*)d_in[5];
    float* out = (float*)d_out;
    const int* src = ei;
    const int* dst = ei + NE;

    void* cnt_ptr = nullptr;
    cudaGetSymbolAddress(&cnt_ptr, g_cnt);
    cudaMemsetAsync(cnt_ptr, 0, NN * sizeof(int));

    k_count_gemm1<<<NBC + NBG, 256>>>(dst, x, W1);   // count ∥ GEMM1
    k_scan1<<<NB, 1024>>>();
    k_scan3<<<NB, 1024>>>();
    k_fill<<<(NE / 4 + 255) / 256, 256>>>(src, dst);
    k_agg1<<<(NN * 32 + 255) / 256, 256>>>(b1);

    k_gemm2<<<(NN + 63) / 64, 320>>>(W2);
    k_agg2<<<(NN * 32 + 255) / 256, 256>>>(b2, out);
}

// round 9
// speedup vs baseline: 1.0697x; 1.0697x over previous
#include <cuda_runtime.h>
#include <cstdint>
#include <math_constants.h>

#define NN 50000
#define NE 800000
#define IND 512
#define HID 64
#define OUTD 40
#define CAP 96    // max degree slots per node; Poisson(16) -> P(>96) ~ 0

#define NBF 782   // fill blocks: NE/4/256 rounded up
#define NBG 391   // gemm1 blocks: NN/128 rounded up

// ---------------- scratch (static device arrays; no allocation) -------------
__device__ int            g_cnt[NN];
__device__ unsigned short g_slot[(size_t)NN * CAP];  // src ids per dst node
__device__ float g_hs1[(size_t)NN * HID];   // raw (x@W1)[i]
__device__ float g_h[(size_t)NN * HID];     // post relu+dropout
__device__ float g_hs2[(size_t)NN * OUTD];  // d^-1/2[i] * (h@W2)[i]

// ---------------- GEMM1 helpers (TF32 tensor cores) --------------------------
__device__ __forceinline__ uint32_t f2tf32(float f) {
    uint32_t r;
    asm("cvt.rna.tf32.f32 %0, %1;" : "=r"(r) : "f"(f));
    return r;
}

__device__ __forceinline__ void mma_tf32(float* c, const uint32_t* a, const uint32_t* b) {
    asm volatile(
        "mma.sync.aligned.m16n8k8.row.col.f32.tf32.tf32.f32 "
        "{%0,%1,%2,%3}, {%4,%5,%6,%7}, {%8,%9}, {%0,%1,%2,%3};"
        : "+f"(c[0]), "+f"(c[1]), "+f"(c[2]), "+f"(c[3])
        : "r"(a[0]), "r"(a[1]), "r"(a[2]), "r"(a[3]), "r"(b[0]), "r"(b[1]));
}

#define XPAD 36
#define WPAD 72

// ---------------- fused: slot fill (blocks < NBF)  ∥  GEMM1 (rest) ----------
__global__ __launch_bounds__(256) void k_fill_gemm1(const int* __restrict__ src,
                                                    const int* __restrict__ dst,
                                                    const float* __restrict__ x,
                                                    const float* __restrict__ W1) {
    __shared__ uint32_t xs[128][XPAD];
    __shared__ uint32_t ws[32][WPAD];

    if (blockIdx.x < NBF) {   // ---- direct slot fill ----
        int i = (blockIdx.x * 256 + threadIdx.x) * 4;
        if (i < NE) {
            int4 s4 = *(const int4*)(src + i);
            int4 d4 = *(const int4*)(dst + i);
            int p0 = atomicAdd(&g_cnt[d4.x], 1);
            int p1 = atomicAdd(&g_cnt[d4.y], 1);
            int p2 = atomicAdd(&g_cnt[d4.z], 1);
            int p3 = atomicAdd(&g_cnt[d4.w], 1);
            if (p0 < CAP) g_slot[(size_t)d4.x * CAP + p0] = (unsigned short)s4.x;
            if (p1 < CAP) g_slot[(size_t)d4.y * CAP + p1] = (unsigned short)s4.y;
            if (p2 < CAP) g_slot[(size_t)d4.z * CAP + p2] = (unsigned short)s4.z;
            if (p3 < CAP) g_slot[(size_t)d4.w * CAP + p3] = (unsigned short)s4.w;
        }
        return;
    }

    // ---- GEMM1 path: hs1 = x @ W1 (raw) ----
    const int row0 = (blockIdx.x - NBF) * 128;
    const int t = threadIdx.x;
    const int wid = t >> 5, lane = t & 31;
    const int wm = wid >> 1, wn = wid & 1;
    const int g = lane >> 2, tig = lane & 3;

    float acc[2][4][4] = {};

    for (int kb = 0; kb < IND; kb += 32) {
#pragma unroll
        for (int i = 0; i < 4; i++) {
            int f = t + 256 * i;
            int r = f >> 3, q = (f & 7) << 2;
            int gr = row0 + r;
            float4 v = make_float4(0.f, 0.f, 0.f, 0.f);
            if (gr < NN) v = *(const float4*)(x + (size_t)gr * IND + kb + q);
            xs[r][q]     = f2tf32(v.x);
            xs[r][q + 1] = f2tf32(v.y);
            xs[r][q + 2] = f2tf32(v.z);
            xs[r][q + 3] = f2tf32(v.w);
        }
#pragma unroll
        for (int i = 0; i < 2; i++) {
            int f = t + 256 * i;
            int kk = f >> 4, c4 = (f & 15) << 2;
            float4 v = *(const float4*)(W1 + (size_t)(kb + kk) * HID + c4);
            ws[kk][c4]     = f2tf32(v.x);
            ws[kk][c4 + 1] = f2tf32(v.y);
            ws[kk][c4 + 2] = f2tf32(v.z);
            ws[kk][c4 + 3] = f2tf32(v.w);
        }
        __syncthreads();
#pragma unroll
        for (int k8 = 0; k8 < 4; k8++) {
            int k0 = k8 * 8;
            uint32_t a[2][4], b[4][2];
#pragma unroll
            for (int i = 0; i < 2; i++) {
                int rb = wm * 32 + i * 16;
                a[i][0] = xs[rb + g][k0 + tig];
                a[i][1] = xs[rb + g + 8][k0 + tig];
                a[i][2] = xs[rb + g][k0 + tig + 4];
                a[i][3] = xs[rb + g + 8][k0 + tig + 4];
            }
#pragma unroll
            for (int j = 0; j < 4; j++) {
                int nb = wn * 32 + j * 8 + g;
                b[j][0] = ws[k0 + tig][nb];
                b[j][1] = ws[k0 + tig + 4][nb];
            }
#pragma unroll
            for (int i = 0; i < 2; i++)
#pragma unroll
                for (int j = 0; j < 4; j++)
                    mma_tf32(acc[i][j], a[i], b[j]);
        }
        __syncthreads();
    }

#pragma unroll
    for (int i = 0; i < 2; i++) {
        int r_lo = row0 + wm * 32 + i * 16 + g;
        int r_hi = r_lo + 8;
#pragma unroll
        for (int j = 0; j < 4; j++) {
            int c = wn * 32 + j * 8 + 2 * tig;
            if (r_lo < NN)
                *(float2*)(g_hs1 + (size_t)r_lo * HID + c) =
                    make_float2(acc[i][j][0], acc[i][j][1]);
            if (r_hi < NN)
                *(float2*)(g_hs1 + (size_t)r_hi * HID + c) =
                    make_float2(acc[i][j][2], acc[i][j][3]);
        }
    }
}

// ---------------- threefry2x32 (JAX partitionable), key (0, 42) -------------
__device__ __forceinline__ uint32_t rotl32(uint32_t x, int r) {
    return (x << r) | (x >> (32 - r));
}

__device__ __forceinline__ uint32_t tf_bits(uint32_t i) {
    uint32_t x0 = 0u, x1 = i;
    const uint32_t k0 = 0u, k1 = 42u, k2 = 0x1BD11BDAu ^ 42u;
    x0 += k0; x1 += k1;
#define TF_ROUND(r) { x0 += x1; x1 = rotl32(x1, r); x1 ^= x0; }
    TF_ROUND(13) TF_ROUND(15) TF_ROUND(26) TF_ROUND(6)
    x0 += k1; x1 += k2 + 1u;
    TF_ROUND(17) TF_ROUND(29) TF_ROUND(16) TF_ROUND(24)
    x0 += k2; x1 += k0 + 2u;
    TF_ROUND(13) TF_ROUND(15) TF_ROUND(26) TF_ROUND(6)
    x0 += k0; x1 += k1 + 3u;
    TF_ROUND(17) TF_ROUND(29) TF_ROUND(16) TF_ROUND(24)
    x0 += k1; x1 += k2 + 4u;
    TF_ROUND(13) TF_ROUND(15) TF_ROUND(26) TF_ROUND(6)
    x0 += k2; x1 += k0 + 5u;
#undef TF_ROUND
    return x0 ^ x1;
}

// ---------------- agg1: warp/node, weights rsqrt(cnt+1) inline --------------
__global__ void k_agg1(const float* __restrict__ b1) {
    int node = blockIdx.x * (blockDim.x >> 5) + (threadIdx.x >> 5);
    if (node >= NN) return;
    int lane = threadIdx.x & 31;
    int c4 = lane & 15, p = lane >> 4;
    const float4* hv = (const float4*)g_hs1;

    int deg = g_cnt[node];
    float dn = rsqrtf((float)(deg + 1));
    const unsigned short* sl = g_slot + (size_t)node * CAP;

    float4 acc = make_float4(0.f, 0.f, 0.f, 0.f);
    if (p == 0) {   // self-loop: dis[node] * ht[node]
        float4 r = hv[(size_t)node * 16 + c4];
        acc.x = dn * r.x; acc.y = dn * r.y; acc.z = dn * r.z; acc.w = dn * r.w;
    }

    int k = p;
    for (; k + 2 < deg; k += 4) {
        int s0 = sl[k];
        int s1 = sl[k + 2];
        float w0 = rsqrtf((float)(__ldg(&g_cnt[s0]) + 1));
        float w1 = rsqrtf((float)(__ldg(&g_cnt[s1]) + 1));
        float4 v0 = hv[(size_t)s0 * 16 + c4];
        float4 v1 = hv[(size_t)s1 * 16 + c4];
        acc.x = fmaf(w0, v0.x, acc.x); acc.y = fmaf(w0, v0.y, acc.y);
        acc.z = fmaf(w0, v0.z, acc.z); acc.w = fmaf(w0, v0.w, acc.w);
        acc.x = fmaf(w1, v1.x, acc.x); acc.y = fmaf(w1, v1.y, acc.y);
        acc.z = fmaf(w1, v1.z, acc.z); acc.w = fmaf(w1, v1.w, acc.w);
    }
    if (k < deg) {
        int s = sl[k];
        float w0 = rsqrtf((float)(__ldg(&g_cnt[s]) + 1));
        float4 v = hv[(size_t)s * 16 + c4];
        acc.x = fmaf(w0, v.x, acc.x); acc.y = fmaf(w0, v.y, acc.y);
        acc.z = fmaf(w0, v.z, acc.z); acc.w = fmaf(w0, v.w, acc.w);
    }

    acc.x += __shfl_down_sync(0xFFFFFFFFu, acc.x, 16);
    acc.y += __shfl_down_sync(0xFFFFFFFFu, acc.y, 16);
    acc.z += __shfl_down_sync(0xFFFFFFFFu, acc.z, 16);
    acc.w += __shfl_down_sync(0xFFFFFFFFu, acc.w, 16);

    if (p == 0) {
        float4 bb = ((const float4*)b1)[c4];
        float4 v;
        v.x = fmaxf(fmaf(dn, acc.x, bb.x), 0.f);
        v.y = fmaxf(fmaf(dn, acc.y, bb.y), 0.f);
        v.z = fmaxf(fmaf(dn, acc.z, bb.z), 0.f);
        v.w = fmaxf(fmaf(dn, acc.w, bb.w), 0.f);
        uint32_t i0 = (uint32_t)node * HID + c4 * 4;
        v.x = (tf_bits(i0)     < 0x80000000u) ? v.x * 2.0f : 0.f;
        v.y = (tf_bits(i0 + 1) < 0x80000000u) ? v.y * 2.0f : 0.f;
        v.z = (tf_bits(i0 + 2) < 0x80000000u) ? v.z * 2.0f : 0.f;
        v.w = (tf_bits(i0 + 3) < 0x80000000u) ? v.w * 2.0f : 0.f;
        ((float4*)g_h)[(size_t)node * 16 + c4] = v;
    }
}

// ---------------- GEMM2: hs2 = dis .* (h @ W2) ------------------------------
__global__ void k_gemm2(const float* __restrict__ W2) {
    __shared__ float hsm[64][65];
    __shared__ float w2s[64][OUTD];
    const int row0 = blockIdx.x * 64;
    const int t = threadIdx.x;

    for (int idx = t; idx < 64 * 64; idx += 320) {
        int r = idx >> 6, k = idx & 63;
        int gr = row0 + r;
        hsm[r][k] = (gr < NN) ? g_h[(size_t)gr * HID + k] : 0.f;
    }
    for (int idx = t; idx < 64 * OUTD; idx += 320)
        w2s[idx / OUTD][idx % OUTD] = W2[idx];
    __syncthreads();

    int r8 = t / OUTD;
    int c = t % OUTD;
    float acc[8] = {};
#pragma unroll
    for (int k = 0; k < 64; k++) {
        float b = w2s[k][c];
#pragma unroll
        for (int i = 0; i < 8; i++)
            acc[i] = fmaf(hsm[r8 * 8 + i][k], b, acc[i]);
    }
#pragma unroll
    for (int i = 0; i < 8; i++) {
        int row = row0 + r8 * 8 + i;
        if (row < NN) {
            float d = rsqrtf((float)(g_cnt[row] + 1));
            g_hs2[(size_t)row * OUTD + c] = d * acc[i];
        }
    }
}

// ---------------- agg2: warp/node, 10 float4 chunks x 3 neighbor slots ------
__global__ void k_agg2(const float* __restrict__ b2, float* __restrict__ out) {
    int node = blockIdx.x * (blockDim.x >> 5) + (threadIdx.x >> 5);
    if (node >= NN) return;
    int lane = threadIdx.x & 31;
    int c = lane % 10;
    int p = (lane < 30) ? (lane / 10) : 3;     // slots 0..2; lanes 30,31 idle
    const float4* hv = (const float4*)g_hs2;   // row stride 10 float4

    int deg = g_cnt[node];
    const unsigned short* sl = g_slot + (size_t)node * CAP;

    float4 acc = make_float4(0.f, 0.f, 0.f, 0.f);
    if (lane < 10) acc = hv[(size_t)node * 10 + c];   // self-loop

    if (p < 3) {
        int k = p;
        for (; k + 3 < deg; k += 6) {
            int s0 = sl[k];
            int s1 = sl[k + 3];
            float4 v0 = hv[(size_t)s0 * 10 + c];
            float4 v1 = hv[(size_t)s1 * 10 + c];
            acc.x += v0.x; acc.y += v0.y; acc.z += v0.z; acc.w += v0.w;
            acc.x += v1.x; acc.y += v1.y; acc.z += v1.z; acc.w += v1.w;
        }
        if (k < deg) {
            int s = sl[k];
            float4 v = hv[(size_t)s * 10 + c];
            acc.x += v.x; acc.y += v.y; acc.z += v.z; acc.w += v.w;
        }
    }

    float rx = acc.x + __shfl_down_sync(0xFFFFFFFFu, acc.x, 10) + __shfl_down_sync(0xFFFFFFFFu, acc.x, 20);
    float ry = acc.y + __shfl_down_sync(0xFFFFFFFFu, acc.y, 10) + __shfl_down_sync(0xFFFFFFFFu, acc.y, 20);
    float rz = acc.z + __shfl_down_sync(0xFFFFFFFFu, acc.z, 10) + __shfl_down_sync(0xFFFFFFFFu, acc.z, 20);
    float rw = acc.w + __shfl_down_sync(0xFFFFFFFFu, acc.w, 10) + __shfl_down_sync(0xFFFFFFFFu, acc.w, 20);

    float4 v = make_float4(-CUDART_INF_F, -CUDART_INF_F, -CUDART_INF_F, -CUDART_INF_F);
    if (lane < 10) {
        float d = rsqrtf((float)(deg + 1));
        float4 bb = ((const float4*)b2)[c];
        v.x = fmaf(d, rx, bb.x);
        v.y = fmaf(d, ry, bb.y);
        v.z = fmaf(d, rz, bb.z);
        v.w = fmaf(d, rw, bb.w);
    }
    float m = fmaxf(fmaxf(v.x, v.y), fmaxf(v.z, v.w));
#pragma unroll
    for (int o = 16; o; o >>= 1) m = fmaxf(m, __shfl_xor_sync(0xFFFFFFFFu, m, o));
    float s = 0.f;
    if (lane < 10)
        s = expf(v.x - m) + expf(v.y - m) + expf(v.z - m) + expf(v.w - m);
#pragma unroll
    for (int o = 16; o; o >>= 1) s += __shfl_xor_sync(0xFFFFFFFFu, s, o);
    float lse = m + logf(s);

    if (lane < 10) {
        float4 o4 = make_float4(v.x - lse, v.y - lse, v.z - lse, v.w - lse);
        ((float4*)out)[(size_t)node * 10 + c] = o4;
    }
}

// ---------------- launch -----------------------------------------------------
extern "C" void kernel_launch(void* const* d_in, const int* in_sizes, int n_in,
                              void* d_out, int out_size) {
    const float* x  = (const float*)d_in[0];
    const int*   ei = (const int*)d_in[1];     // [2, NE] row-major
    const float* W1 = (const float*)d_in[2];
    const float* b1 = (const float*)d_in[3];
    const float* W2 = (const float*)d_in[4];
    const float* b2 = (const float*)d_in[5];
    float* out = (float*)d_out;
    const int* src = ei;
    const int* dst = ei + NE;

    void* cnt_ptr = nullptr;
    cudaGetSymbolAddress(&cnt_ptr, g_cnt);
    cudaMemsetAsync(cnt_ptr, 0, NN * sizeof(int));

    k_fill_gemm1<<<NBF + NBG, 256>>>(src, dst, x, W1);   // slot fill ∥ GEMM1
    k_agg1<<<(NN * 32 + 255) / 256, 256>>>(b1);
    k_gemm2<<<(NN + 63) / 64, 320>>>(W2);
    k_agg2<<<(NN * 32 + 255) / 256, 256>>>(b2, out);
}

// round 10
// speedup vs baseline: 1.2941x; 1.2098x over previous
#include <cuda_runtime.h>
#include <cstdint>
#include <math_constants.h>

#define NN 50000
#define NE 800000
#define IND 512
#define HID 64
#define OUTD 40
#define CAP 96    // max degree slots per node; Poisson(16) -> P(>96) ~ 0

#define NBF 782   // fill blocks: NE/4/256 rounded up
#define NBG 391   // gemm1 blocks: NN/128 rounded up

// ---------------- scratch (static device arrays; no allocation) -------------
__device__ int            g_cnt[NN];
__device__ unsigned short g_slot[(size_t)NN * CAP];  // src ids per dst node
__device__ float g_hs1[(size_t)NN * HID];   // raw (x@W1)[i]
__device__ float g_h[(size_t)NN * HID];     // post relu+dropout
__device__ float g_hs2[(size_t)NN * OUTD];  // d^-1/2[i] * (h@W2)[i]

// ---------------- GEMM1 helpers (TF32 tensor cores) --------------------------
__device__ __forceinline__ uint32_t f2tf32(float f) {
    uint32_t r;
    asm("cvt.rna.tf32.f32 %0, %1;" : "=r"(r) : "f"(f));
    return r;
}

__device__ __forceinline__ void mma_tf32(float* c, const uint32_t* a, const uint32_t* b) {
    asm volatile(
        "mma.sync.aligned.m16n8k8.row.col.f32.tf32.tf32.f32 "
        "{%0,%1,%2,%3}, {%4,%5,%6,%7}, {%8,%9}, {%0,%1,%2,%3};"
        : "+f"(c[0]), "+f"(c[1]), "+f"(c[2]), "+f"(c[3])
        : "r"(a[0]), "r"(a[1]), "r"(a[2]), "r"(a[3]), "r"(b[0]), "r"(b[1]));
}

#define XPAD 36
#define WPAD 72

// ---------------- fused: slot fill (blocks < NBF)  ∥  GEMM1 (rest) ----------
__global__ __launch_bounds__(256) void k_fill_gemm1(const int* __restrict__ src,
                                                    const int* __restrict__ dst,
                                                    const float* __restrict__ x,
                                                    const float* __restrict__ W1) {
    __shared__ uint32_t xs[128][XPAD];
    __shared__ uint32_t ws[32][WPAD];

    if (blockIdx.x < NBF) {   // ---- direct slot fill ----
        int i = (blockIdx.x * 256 + threadIdx.x) * 4;
        if (i < NE) {
            int4 s4 = *(const int4*)(src + i);
            int4 d4 = *(const int4*)(dst + i);
            int p0 = atomicAdd(&g_cnt[d4.x], 1);
            int p1 = atomicAdd(&g_cnt[d4.y], 1);
            int p2 = atomicAdd(&g_cnt[d4.z], 1);
            int p3 = atomicAdd(&g_cnt[d4.w], 1);
            if (p0 < CAP) g_slot[(size_t)d4.x * CAP + p0] = (unsigned short)s4.x;
            if (p1 < CAP) g_slot[(size_t)d4.y * CAP + p1] = (unsigned short)s4.y;
            if (p2 < CAP) g_slot[(size_t)d4.z * CAP + p2] = (unsigned short)s4.z;
            if (p3 < CAP) g_slot[(size_t)d4.w * CAP + p3] = (unsigned short)s4.w;
        }
        return;
    }

    // ---- GEMM1 path: hs1 = x @ W1 (raw), register prefetch on x ----
    const int row0 = (blockIdx.x - NBF) * 128;
    const int t = threadIdx.x;
    const int wid = t >> 5, lane = t & 31;
    const int wm = wid >> 1, wn = wid & 1;
    const int g = lane >> 2, tig = lane & 3;

    // per-thread x-tile coords (kb-invariant)
    int xr_r[4], xr_q[4];
    bool xr_ok[4];
#pragma unroll
    for (int i = 0; i < 4; i++) {
        int f = t + 256 * i;
        xr_r[i] = f >> 3;
        xr_q[i] = (f & 7) << 2;
        xr_ok[i] = (row0 + xr_r[i]) < NN;
    }

    float4 xr[4];
#pragma unroll
    for (int i = 0; i < 4; i++) {
        xr[i] = make_float4(0.f, 0.f, 0.f, 0.f);
        if (xr_ok[i]) xr[i] = *(const float4*)(x + (size_t)(row0 + xr_r[i]) * IND + xr_q[i]);
    }

    float acc[2][4][4] = {};

    for (int kb = 0; kb < IND; kb += 32) {
        // store prefetched x tile
#pragma unroll
        for (int i = 0; i < 4; i++) {
            int r = xr_r[i], q = xr_q[i];
            xs[r][q]     = f2tf32(xr[i].x);
            xs[r][q + 1] = f2tf32(xr[i].y);
            xs[r][q + 2] = f2tf32(xr[i].z);
            xs[r][q + 3] = f2tf32(xr[i].w);
        }
        // W tile (L2-hot after first wave)
#pragma unroll
        for (int i = 0; i < 2; i++) {
            int f = t + 256 * i;
            int kk = f >> 4, c4 = (f & 15) << 2;
            float4 v = *(const float4*)(W1 + (size_t)(kb + kk) * HID + c4);
            ws[kk][c4]     = f2tf32(v.x);
            ws[kk][c4 + 1] = f2tf32(v.y);
            ws[kk][c4 + 2] = f2tf32(v.z);
            ws[kk][c4 + 3] = f2tf32(v.w);
        }
        __syncthreads();

        // issue next x-tile loads; latency hidden behind the mma block
        if (kb + 32 < IND) {
#pragma unroll
            for (int i = 0; i < 4; i++)
                if (xr_ok[i])
                    xr[i] = *(const float4*)(x + (size_t)(row0 + xr_r[i]) * IND + (kb + 32) + xr_q[i]);
        }

#pragma unroll
        for (int k8 = 0; k8 < 4; k8++) {
            int k0 = k8 * 8;
            uint32_t a[2][4], b[4][2];
#pragma unroll
            for (int i = 0; i < 2; i++) {
                int rb = wm * 32 + i * 16;
                a[i][0] = xs[rb + g][k0 + tig];
                a[i][1] = xs[rb + g + 8][k0 + tig];
                a[i][2] = xs[rb + g][k0 + tig + 4];
                a[i][3] = xs[rb + g + 8][k0 + tig + 4];
            }
#pragma unroll
            for (int j = 0; j < 4; j++) {
                int nb = wn * 32 + j * 8 + g;
                b[j][0] = ws[k0 + tig][nb];
                b[j][1] = ws[k0 + tig + 4][nb];
            }
#pragma unroll
            for (int i = 0; i < 2; i++)
#pragma unroll
                for (int j = 0; j < 4; j++)
                    mma_tf32(acc[i][j], a[i], b[j]);
        }
        __syncthreads();
    }

#pragma unroll
    for (int i = 0; i < 2; i++) {
        int r_lo = row0 + wm * 32 + i * 16 + g;
        int r_hi = r_lo + 8;
#pragma unroll
        for (int j = 0; j < 4; j++) {
            int c = wn * 32 + j * 8 + 2 * tig;
            if (r_lo < NN)
                *(float2*)(g_hs1 + (size_t)r_lo * HID + c) =
                    make_float2(acc[i][j][0], acc[i][j][1]);
            if (r_hi < NN)
                *(float2*)(g_hs1 + (size_t)r_hi * HID + c) =
                    make_float2(acc[i][j][2], acc[i][j][3]);
        }
    }
}

// ---------------- threefry2x32 (JAX partitionable), key (0, 42) -------------
__device__ __forceinline__ uint32_t rotl32(uint32_t x, int r) {
    return (x << r) | (x >> (32 - r));
}

__device__ __forceinline__ uint32_t tf_bits(uint32_t i) {
    uint32_t x0 = 0u, x1 = i;
    const uint32_t k0 = 0u, k1 = 42u, k2 = 0x1BD11BDAu ^ 42u;
    x0 += k0; x1 += k1;
#define TF_ROUND(r) { x0 += x1; x1 = rotl32(x1, r); x1 ^= x0; }
    TF_ROUND(13) TF_ROUND(15) TF_ROUND(26) TF_ROUND(6)
    x0 += k1; x1 += k2 + 1u;
    TF_ROUND(17) TF_ROUND(29) TF_ROUND(16) TF_ROUND(24)
    x0 += k2; x1 += k0 + 2u;
    TF_ROUND(13) TF_ROUND(15) TF_ROUND(26) TF_ROUND(6)
    x0 += k0; x1 += k1 + 3u;
    TF_ROUND(17) TF_ROUND(29) TF_ROUND(16) TF_ROUND(24)
    x0 += k1; x1 += k2 + 4u;
    TF_ROUND(13) TF_ROUND(15) TF_ROUND(26) TF_ROUND(6)
    x0 += k2; x1 += k0 + 5u;
#undef TF_ROUND
    return x0 ^ x1;
}

// ---------------- agg1: warp/node, 2 slots x unroll 3 -----------------------
__global__ void k_agg1(const float* __restrict__ b1) {
    int node = blockIdx.x * (blockDim.x >> 5) + (threadIdx.x >> 5);
    if (node >= NN) return;
    int lane = threadIdx.x & 31;
    int c4 = lane & 15, p = lane >> 4;
    const float4* hv = (const float4*)g_hs1;

    int deg = g_cnt[node];
    float dn = rsqrtf((float)(deg + 1));
    const unsigned short* sl = g_slot + (unsigned)node * CAP;

    float4 acc = make_float4(0.f, 0.f, 0.f, 0.f);
    if (p == 0) {   // self-loop: dis[node] * ht[node]
        float4 r = hv[(unsigned)(node * 16 + c4)];
        acc.x = dn * r.x; acc.y = dn * r.y; acc.z = dn * r.z; acc.w = dn * r.w;
    }

#define A1_STEP(KK) {                                                   \
        int s_ = sl[KK];                                                \
        float w_ = rsqrtf((float)(__ldg(&g_cnt[s_]) + 1));              \
        float4 v_ = hv[(unsigned)(s_ * 16 + c4)];                       \
        acc.x = fmaf(w_, v_.x, acc.x); acc.y = fmaf(w_, v_.y, acc.y);   \
        acc.z = fmaf(w_, v_.z, acc.z); acc.w = fmaf(w_, v_.w, acc.w); }

    int k = p;
    for (; k + 4 < deg; k += 6) {   // 3 rows in flight per slot
        A1_STEP(k) A1_STEP(k + 2) A1_STEP(k + 4)
    }
    for (; k < deg; k += 2) A1_STEP(k)
#undef A1_STEP

    acc.x += __shfl_down_sync(0xFFFFFFFFu, acc.x, 16);
    acc.y += __shfl_down_sync(0xFFFFFFFFu, acc.y, 16);
    acc.z += __shfl_down_sync(0xFFFFFFFFu, acc.z, 16);
    acc.w += __shfl_down_sync(0xFFFFFFFFu, acc.w, 16);

    if (p == 0) {
        float4 bb = ((const float4*)b1)[c4];
        float4 v;
        v.x = fmaxf(fmaf(dn, acc.x, bb.x), 0.f);
        v.y = fmaxf(fmaf(dn, acc.y, bb.y), 0.f);
        v.z = fmaxf(fmaf(dn, acc.z, bb.z), 0.f);
        v.w = fmaxf(fmaf(dn, acc.w, bb.w), 0.f);
        uint32_t i0 = (uint32_t)node * HID + c4 * 4;
        v.x = (tf_bits(i0)     < 0x80000000u) ? v.x * 2.0f : 0.f;
        v.y = (tf_bits(i0 + 1) < 0x80000000u) ? v.y * 2.0f : 0.f;
        v.z = (tf_bits(i0 + 2) < 0x80000000u) ? v.z * 2.0f : 0.f;
        v.w = (tf_bits(i0 + 3) < 0x80000000u) ? v.w * 2.0f : 0.f;
        ((float4*)g_h)[(unsigned)(node * 16 + c4)] = v;
    }
}

// ---------------- GEMM2: hs2 = dis .* (h @ W2) ------------------------------
__global__ void k_gemm2(const float* __restrict__ W2) {
    __shared__ float hsm[64][65];
    __shared__ float w2s[64][OUTD];
    const int row0 = blockIdx.x * 64;
    const int t = threadIdx.x;

    for (int idx = t; idx < 64 * 64; idx += 320) {
        int r = idx >> 6, k = idx & 63;
        int gr = row0 + r;
        hsm[r][k] = (gr < NN) ? g_h[(unsigned)(gr * HID + k)] : 0.f;
    }
    for (int idx = t; idx < 64 * OUTD; idx += 320)
        w2s[idx / OUTD][idx % OUTD] = W2[idx];
    __syncthreads();

    int r8 = t / OUTD;
    int c = t % OUTD;
    float acc[8] = {};
#pragma unroll
    for (int k = 0; k < 64; k++) {
        float b = w2s[k][c];
#pragma unroll
        for (int i = 0; i < 8; i++)
            acc[i] = fmaf(hsm[r8 * 8 + i][k], b, acc[i]);
    }
#pragma unroll
    for (int i = 0; i < 8; i++) {
        int row = row0 + r8 * 8 + i;
        if (row < NN) {
            float d = rsqrtf((float)(g_cnt[row] + 1));
            g_hs2[(unsigned)(row * OUTD + c)] = d * acc[i];
        }
    }
}

// ---------------- agg2: warp/node, 3 slots x unroll 3 -----------------------
__global__ void k_agg2(const float* __restrict__ b2, float* __restrict__ out) {
    int node = blockIdx.x * (blockDim.x >> 5) + (threadIdx.x >> 5);
    if (node >= NN) return;
    int lane = threadIdx.x & 31;
    int c = lane % 10;
    int p = (lane < 30) ? (lane / 10) : 3;     // slots 0..2; lanes 30,31 idle
    const float4* hv = (const float4*)g_hs2;   // row stride 10 float4

    int deg = g_cnt[node];
    const unsigned short* sl = g_slot + (unsigned)node * CAP;

    float4 acc = make_float4(0.f, 0.f, 0.f, 0.f);
    if (lane < 10) acc = hv[(unsigned)(node * 10 + c)];   // self-loop

#define A2_STEP(KK) {                                           \
        int s_ = sl[KK];                                        \
        float4 v_ = hv[(unsigned)(s_ * 10 + c)];                \
        acc.x += v_.x; acc.y += v_.y; acc.z += v_.z; acc.w += v_.w; }

    if (p < 3) {
        int k = p;
        for (; k + 6 < deg; k += 9) {   // 3 rows in flight per slot
            A2_STEP(k) A2_STEP(k + 3) A2_STEP(k + 6)
        }
        for (; k < deg; k += 3) A2_STEP(k)
    }
#undef A2_STEP

    float rx = acc.x + __shfl_down_sync(0xFFFFFFFFu, acc.x, 10) + __shfl_down_sync(0xFFFFFFFFu, acc.x, 20);
    float ry = acc.y + __shfl_down_sync(0xFFFFFFFFu, acc.y, 10) + __shfl_down_sync(0xFFFFFFFFu, acc.y, 20);
    float rz = acc.z + __shfl_down_sync(0xFFFFFFFFu, acc.z, 10) + __shfl_down_sync(0xFFFFFFFFu, acc.z, 20);
    float rw = acc.w + __shfl_down_sync(0xFFFFFFFFu, acc.w, 10) + __shfl_down_sync(0xFFFFFFFFu, acc.w, 20);

    float4 v = make_float4(-CUDART_INF_F, -CUDART_INF_F, -CUDART_INF_F, -CUDART_INF_F);
    if (lane < 10) {
        float d = rsqrtf((float)(deg + 1));
        float4 bb = ((const float4*)b2)[c];
        v.x = fmaf(d, rx, bb.x);
        v.y = fmaf(d, ry, bb.y);
        v.z = fmaf(d, rz, bb.z);
        v.w = fmaf(d, rw, bb.w);
    }
    float m = fmaxf(fmaxf(v.x, v.y), fmaxf(v.z, v.w));
#pragma unroll
    for (int o = 16; o; o >>= 1) m = fmaxf(m, __shfl_xor_sync(0xFFFFFFFFu, m, o));
    float s = 0.f;
    if (lane < 10)
        s = expf(v.x - m) + expf(v.y - m) + expf(v.z - m) + expf(v.w - m);
#pragma unroll
    for (int o = 16; o; o >>= 1) s += __shfl_xor_sync(0xFFFFFFFFu, s, o);
    float lse = m + logf(s);

    if (lane < 10) {
        float4 o4 = make_float4(v.x - lse, v.y - lse, v.z - lse, v.w - lse);
        ((float4*)out)[(unsigned)(node * 10 + c)] = o4;
    }
}

// ---------------- launch -----------------------------------------------------
extern "C" void kernel_launch(void* const* d_in, const int* in_sizes, int n_in,
                              void* d_out, int out_size) {
    const float* x  = (const float*)d_in[0];
    const int*   ei = (const int*)d_in[1];     // [2, NE] row-major
    const float* W1 = (const float*)d_in[2];
    const float* b1 = (const float*)d_in[3];
    const float* W2 = (const float*)d_in[4];
    const float* b2 = (const float*)d_in[5];
    float* out = (float*)d_out;
    const int* src = ei;
    const int* dst = ei + NE;

    void* cnt_ptr = nullptr;
    cudaGetSymbolAddress(&cnt_ptr, g_cnt);
    cudaMemsetAsync(cnt_ptr, 0, NN * sizeof(int));

    k_fill_gemm1<<<NBF + NBG, 256>>>(src, dst, x, W1);   // slot fill ∥ GEMM1
    k_agg1<<<(NN * 32 + 255) / 256, 256>>>(b1);
    k_gemm2<<<(NN + 63) / 64, 320>>>(W2);
    k_agg2<<<(NN * 32 + 255) / 256, 256>>>(b2, out);
}

// round 12
// speedup vs baseline: 1.4194x; 1.0968x over previous
#include <cuda_runtime.h>
#include <cuda_fp16.h>
#include <cstdint>
#include <math_constants.h>

#define NN 50000
#define NE 800000
#define IND 512
#define HID 64
#define OUTD 40
#define CAP 96    // max degree slots per node; Poisson(16) -> P(>96) ~ 0

#define NBF 782   // fill blocks: NE/4/256 rounded up
#define NBG 391   // gemm1 blocks: NN/128 rounded up

// ---------------- scratch (static device arrays; no allocation) -------------
__device__ int            g_cnt[NN];
__device__ unsigned short g_slot[(size_t)NN * CAP];          // src ids per dst node
__device__ __align__(16) __half g_hs1h[(size_t)NN * HID];    // raw (x@W1), fp16
__device__ __align__(16) float  g_h[(size_t)NN * HID];       // relu(d*agg+b), PRE-dropout
__device__ __align__(16) __half g_hs2h[(size_t)NN * 64];     // d*(h@W2), fp16, padded 64/row

// ---------------- GEMM1 helpers (TF32 tensor cores) --------------------------
__device__ __forceinline__ uint32_t f2tf32(float f) {
    uint32_t r;
    asm("cvt.rna.tf32.f32 %0, %1;" : "=r"(r) : "f"(f));
    return r;
}

__device__ __forceinline__ void mma_tf32(float* c, const uint32_t* a, const uint32_t* b) {
    asm volatile(
        "mma.sync.aligned.m16n8k8.row.col.f32.tf32.tf32.f32 "
        "{%0,%1,%2,%3}, {%4,%5,%6,%7}, {%8,%9}, {%0,%1,%2,%3};"
        : "+f"(c[0]), "+f"(c[1]), "+f"(c[2]), "+f"(c[3])
        : "r"(a[0]), "r"(a[1]), "r"(a[2]), "r"(a[3]), "r"(b[0]), "r"(b[1]));
}

#define XPAD 36
#define WPAD 72

// ---------------- fused: slot fill (blocks < NBF)  ∥  GEMM1 (rest) ----------
__global__ __launch_bounds__(256) void k_fill_gemm1(const int* __restrict__ src,
                                                    const int* __restrict__ dst,
                                                    const float* __restrict__ x,
                                                    const float* __restrict__ W1) {
    __shared__ uint32_t xs[128][XPAD];
    __shared__ uint32_t ws[32][WPAD];

    if (blockIdx.x < NBF) {   // ---- direct slot fill ----
        int i = (blockIdx.x * 256 + threadIdx.x) * 4;
        if (i < NE) {
            int4 s4 = *(const int4*)(src + i);
            int4 d4 = *(const int4*)(dst + i);
            int p0 = atomicAdd(&g_cnt[d4.x], 1);
            int p1 = atomicAdd(&g_cnt[d4.y], 1);
            int p2 = atomicAdd(&g_cnt[d4.z], 1);
            int p3 = atomicAdd(&g_cnt[d4.w], 1);
            if (p0 < CAP) g_slot[(size_t)d4.x * CAP + p0] = (unsigned short)s4.x;
            if (p1 < CAP) g_slot[(size_t)d4.y * CAP + p1] = (unsigned short)s4.y;
            if (p2 < CAP) g_slot[(size_t)d4.z * CAP + p2] = (unsigned short)s4.z;
            if (p3 < CAP) g_slot[(size_t)d4.w * CAP + p3] = (unsigned short)s4.w;
        }
        return;
    }

    // ---- GEMM1 path: hs1 = x @ W1 (raw), register prefetch on x ----
    const int row0 = (blockIdx.x - NBF) * 128;
    const int t = threadIdx.x;
    const int wid = t >> 5, lane = t & 31;
    const int wm = wid >> 1, wn = wid & 1;
    const int g = lane >> 2, tig = lane & 3;

    int xr_r[4], xr_q[4];
    bool xr_ok[4];
#pragma unroll
    for (int i = 0; i < 4; i++) {
        int f = t + 256 * i;
        xr_r[i] = f >> 3;
        xr_q[i] = (f & 7) << 2;
        xr_ok[i] = (row0 + xr_r[i]) < NN;
    }

    float4 xr[4];
#pragma unroll
    for (int i = 0; i < 4; i++) {
        xr[i] = make_float4(0.f, 0.f, 0.f, 0.f);
        if (xr_ok[i]) xr[i] = *(const float4*)(x + (size_t)(row0 + xr_r[i]) * IND + xr_q[i]);
    }

    float acc[2][4][4] = {};

    for (int kb = 0; kb < IND; kb += 32) {
#pragma unroll
        for (int i = 0; i < 4; i++) {
            int r = xr_r[i], q = xr_q[i];
            xs[r][q]     = f2tf32(xr[i].x);
            xs[r][q + 1] = f2tf32(xr[i].y);
            xs[r][q + 2] = f2tf32(xr[i].z);
            xs[r][q + 3] = f2tf32(xr[i].w);
        }
#pragma unroll
        for (int i = 0; i < 2; i++) {
            int f = t + 256 * i;
            int kk = f >> 4, c4 = (f & 15) << 2;
            float4 v = *(const float4*)(W1 + (size_t)(kb + kk) * HID + c4);
            ws[kk][c4]     = f2tf32(v.x);
            ws[kk][c4 + 1] = f2tf32(v.y);
            ws[kk][c4 + 2] = f2tf32(v.z);
            ws[kk][c4 + 3] = f2tf32(v.w);
        }
        __syncthreads();

        if (kb + 32 < IND) {
#pragma unroll
            for (int i = 0; i < 4; i++)
                if (xr_ok[i])
                    xr[i] = *(const float4*)(x + (size_t)(row0 + xr_r[i]) * IND + (kb + 32) + xr_q[i]);
        }

#pragma unroll
        for (int k8 = 0; k8 < 4; k8++) {
            int k0 = k8 * 8;
            uint32_t a[2][4], b[4][2];
#pragma unroll
            for (int i = 0; i < 2; i++) {
                int rb = wm * 32 + i * 16;
                a[i][0] = xs[rb + g][k0 + tig];
                a[i][1] = xs[rb + g + 8][k0 + tig];
                a[i][2] = xs[rb + g][k0 + tig + 4];
                a[i][3] = xs[rb + g + 8][k0 + tig + 4];
            }
#pragma unroll
            for (int j = 0; j < 4; j++) {
                int nb = wn * 32 + j * 8 + g;
                b[j][0] = ws[k0 + tig][nb];
                b[j][1] = ws[k0 + tig + 4][nb];
            }
#pragma unroll
            for (int i = 0; i < 2; i++)
#pragma unroll
                for (int j = 0; j < 4; j++)
                    mma_tf32(acc[i][j], a[i], b[j]);
        }
        __syncthreads();
    }

    // epilogue: store fp16 (adjacent col pairs -> one half2)
#pragma unroll
    for (int i = 0; i < 2; i++) {
        int r_lo = row0 + wm * 32 + i * 16 + g;
        int r_hi = r_lo + 8;
#pragma unroll
        for (int j = 0; j < 4; j++) {
            int c = wn * 32 + j * 8 + 2 * tig;
            if (r_lo < NN)
                *(__half2*)(g_hs1h + (unsigned)(r_lo * HID + c)) =
                    __floats2half2_rn(acc[i][j][0], acc[i][j][1]);
            if (r_hi < NN)
                *(__half2*)(g_hs1h + (unsigned)(r_hi * HID + c)) =
                    __floats2half2_rn(acc[i][j][2], acc[i][j][3]);
        }
    }
}

// ---------------- threefry2x32 (JAX partitionable), key (0, 42) -------------
__device__ __forceinline__ uint32_t rotl32(uint32_t x, int r) {
    return (x << r) | (x >> (32 - r));
}

__device__ __forceinline__ uint32_t tf_bits(uint32_t i) {
    uint32_t x0 = 0u, x1 = i;
    const uint32_t k0 = 0u, k1 = 42u, k2 = 0x1BD11BDAu ^ 42u;
    x0 += k0; x1 += k1;
#define TF_ROUND(r) { x0 += x1; x1 = rotl32(x1, r); x1 ^= x0; }
    TF_ROUND(13) TF_ROUND(15) TF_ROUND(26) TF_ROUND(6)
    x0 += k1; x1 += k2 + 1u;
    TF_ROUND(17) TF_ROUND(29) TF_ROUND(16) TF_ROUND(24)
    x0 += k2; x1 += k0 + 2u;
    TF_ROUND(13) TF_ROUND(15) TF_ROUND(26) TF_ROUND(6)
    x0 += k0; x1 += k1 + 3u;
    TF_ROUND(17) TF_ROUND(29) TF_ROUND(16) TF_ROUND(24)
    x0 += k1; x1 += k2 + 4u;
    TF_ROUND(13) TF_ROUND(15) TF_ROUND(26) TF_ROUND(6)
    x0 += k2; x1 += k0 + 5u;
#undef TF_ROUND
    return x0 ^ x1;
}

// ---------------- agg1: warp/node, 8 chunk-lanes x 4 slots, unroll 3 --------
// hs1 row = 64 half = 128B = 8 uint4; NO dropout here (moved to gemm2 load)
__global__ void k_agg1(const float* __restrict__ b1) {
    int node = blockIdx.x * (blockDim.x >> 5) + (threadIdx.x >> 5);
    if (node >= NN) return;
    int lane = threadIdx.x & 31;
    int c8 = lane & 7, p = lane >> 3;           // chunk, slot
    const uint4* hv = (const uint4*)g_hs1h;     // row stride 8 uint4

    int deg = g_cnt[node];
    float dn = rsqrtf((float)(deg + 1));
    const unsigned short* sl = g_slot + (unsigned)node * CAP;

    float4 a0 = make_float4(0.f, 0.f, 0.f, 0.f);
    float4 a1 = make_float4(0.f, 0.f, 0.f, 0.f);
    if (p == 0) {   // self-loop
        uint4 r = hv[(unsigned)(node * 8 + c8)];
        float2 f0 = __half22float2(*(__half2*)&r.x);
        float2 f1 = __half22float2(*(__half2*)&r.y);
        float2 f2 = __half22float2(*(__half2*)&r.z);
        float2 f3 = __half22float2(*(__half2*)&r.w);
        a0.x = dn * f0.x; a0.y = dn * f0.y; a0.z = dn * f1.x; a0.w = dn * f1.y;
        a1.x = dn * f2.x; a1.y = dn * f2.y; a1.z = dn * f3.x; a1.w = dn * f3.y;
    }

#define A1_STEP(KK) {                                                    \
        int s_ = sl[KK];                                                 \
        float w_ = rsqrtf((float)(__ldg(&g_cnt[s_]) + 1));               \
        uint4 v_ = hv[(unsigned)(s_ * 8 + c8)];                          \
        float2 f0_ = __half22float2(*(__half2*)&v_.x);                   \
        float2 f1_ = __half22float2(*(__half2*)&v_.y);                   \
        float2 f2_ = __half22float2(*(__half2*)&v_.z);                   \
        float2 f3_ = __half22float2(*(__half2*)&v_.w);                   \
        a0.x = fmaf(w_, f0_.x, a0.x); a0.y = fmaf(w_, f0_.y, a0.y);      \
        a0.z = fmaf(w_, f1_.x, a0.z); a0.w = fmaf(w_, f1_.y, a0.w);      \
        a1.x = fmaf(w_, f2_.x, a1.x); a1.y = fmaf(w_, f2_.y, a1.y);      \
        a1.z = fmaf(w_, f3_.x, a1.z); a1.w = fmaf(w_, f3_.y, a1.w); }

    int k = p;
    for (; k + 8 < deg; k += 12) {   // 3 rows in flight per slot x 4 slots
        A1_STEP(k) A1_STEP(k + 4) A1_STEP(k + 8)
    }
    for (; k < deg; k += 4) A1_STEP(k)
#undef A1_STEP

    // combine 4 slots -> lanes 0..7
    a0.x += __shfl_down_sync(0xFFFFFFFFu, a0.x, 16);
    a0.y += __shfl_down_sync(0xFFFFFFFFu, a0.y, 16);
    a0.z += __shfl_down_sync(0xFFFFFFFFu, a0.z, 16);
    a0.w += __shfl_down_sync(0xFFFFFFFFu, a0.w, 16);
    a1.x += __shfl_down_sync(0xFFFFFFFFu, a1.x, 16);
    a1.y += __shfl_down_sync(0xFFFFFFFFu, a1.y, 16);
    a1.z += __shfl_down_sync(0xFFFFFFFFu, a1.z, 16);
    a1.w += __shfl_down_sync(0xFFFFFFFFu, a1.w, 16);
    a0.x += __shfl_down_sync(0xFFFFFFFFu, a0.x, 8);
    a0.y += __shfl_down_sync(0xFFFFFFFFu, a0.y, 8);
    a0.z += __shfl_down_sync(0xFFFFFFFFu, a0.z, 8);
    a0.w += __shfl_down_sync(0xFFFFFFFFu, a0.w, 8);
    a1.x += __shfl_down_sync(0xFFFFFFFFu, a1.x, 8);
    a1.y += __shfl_down_sync(0xFFFFFFFFu, a1.y, 8);
    a1.z += __shfl_down_sync(0xFFFFFFFFu, a1.z, 8);
    a1.w += __shfl_down_sync(0xFFFFFFFFu, a1.w, 8);

    if (p == 0) {   // lanes 0..7: bias + relu, store fp32 (pre-dropout)
        float4 b0 = ((const float4*)b1)[c8 * 2];
        float4 b2v = ((const float4*)b1)[c8 * 2 + 1];
        float4 v0, v1;
        v0.x = fmaxf(fmaf(dn, a0.x, b0.x), 0.f);
        v0.y = fmaxf(fmaf(dn, a0.y, b0.y), 0.f);
        v0.z = fmaxf(fmaf(dn, a0.z, b0.z), 0.f);
        v0.w = fmaxf(fmaf(dn, a0.w, b0.w), 0.f);
        v1.x = fmaxf(fmaf(dn, a1.x, b2v.x), 0.f);
        v1.y = fmaxf(fmaf(dn, a1.y, b2v.y), 0.f);
        v1.z = fmaxf(fmaf(dn, a1.z, b2v.z), 0.f);
        v1.w = fmaxf(fmaf(dn, a1.w, b2v.w), 0.f);
        ((float4*)g_h)[(unsigned)(node * 16 + c8 * 2)]     = v0;
        ((float4*)g_h)[(unsigned)(node * 16 + c8 * 2 + 1)] = v1;
    }
}

// ---------------- GEMM2: hs2 = dis .* (dropout(h) @ W2), fp16 out -----------
__global__ void k_gemm2(const float* __restrict__ W2) {
    __shared__ float hsm[64][65];
    __shared__ float w2s[64][OUTD];
    const int row0 = blockIdx.x * 64;
    const int t = threadIdx.x;

    for (int idx = t; idx < 64 * 64; idx += 320) {
        int r = idx >> 6, k = idx & 63;
        int gr = row0 + r;
        float val = 0.f;
        if (gr < NN) {
            uint32_t i0 = (uint32_t)gr * HID + k;
            val = g_h[i0];
            val = (tf_bits(i0) < 0x80000000u) ? val * 2.0f : 0.f;   // dropout here
        }
        hsm[r][k] = val;
    }
    for (int idx = t; idx < 64 * OUTD; idx += 320)
        w2s[idx / OUTD][idx % OUTD] = W2[idx];
    __syncthreads();

    int r8 = t / OUTD;
    int c = t % OUTD;
    float acc[8] = {};
#pragma unroll
    for (int k = 0; k < 64; k++) {
        float b = w2s[k][c];
#pragma unroll
        for (int i = 0; i < 8; i++)
            acc[i] = fmaf(hsm[r8 * 8 + i][k], b, acc[i]);
    }
#pragma unroll
    for (int i = 0; i < 8; i++) {
        int row = row0 + r8 * 8 + i;
        if (row < NN) {
            float d = rsqrtf((float)(g_cnt[row] + 1));
            g_hs2h[(unsigned)(row * 64 + c)] = __float2half(d * acc[i]);
        }
    }
}

// ---------------- agg2: warp/node, 10 chunk-lanes x 3 slots, unroll 4 -------
// hs2 row = 64 half padded = 128B = 16 uint2; first 10 uint2 (40 half) used
__global__ void k_agg2(const float* __restrict__ b2, float* __restrict__ out) {
    int node = blockIdx.x * (blockDim.x >> 5) + (threadIdx.x >> 5);
    if (node >= NN) return;
    int lane = threadIdx.x & 31;
    int c = lane % 10;
    int p = (lane < 30) ? (lane / 10) : 3;     // slots 0..2; lanes 30,31 idle
    const uint2* hv = (const uint2*)g_hs2h;    // row stride 16 uint2; use first 10

    int deg = g_cnt[node];
    const unsigned short* sl = g_slot + (unsigned)node * CAP;

    float4 acc = make_float4(0.f, 0.f, 0.f, 0.f);
    if (lane < 10) {   // self-loop
        uint2 r = hv[(unsigned)(node * 16 + c)];
        float2 f0 = __half22float2(*(__half2*)&r.x);
        float2 f1 = __half22float2(*(__half2*)&r.y);
        acc.x = f0.x; acc.y = f0.y; acc.z = f1.x; acc.w = f1.y;
    }

#define A2_STEP(KK) {                                           \
        int s_ = sl[KK];                                        \
        uint2 v_ = hv[(unsigned)(s_ * 16 + c)];                 \
        float2 f0_ = __half22float2(*(__half2*)&v_.x);          \
        float2 f1_ = __half22float2(*(__half2*)&v_.y);          \
        acc.x += f0_.x; acc.y += f0_.y;                         \
        acc.z += f1_.x; acc.w += f1_.y; }

    if (p < 3) {
        int k = p;
        for (; k + 9 < deg; k += 12) {   // 4 rows in flight per slot x 3 slots
            A2_STEP(k) A2_STEP(k + 3) A2_STEP(k + 6) A2_STEP(k + 9)
        }
        for (; k < deg; k += 3) A2_STEP(k)
    }
#undef A2_STEP

    float rx = acc.x + __shfl_down_sync(0xFFFFFFFFu, acc.x, 10) + __shfl_down_sync(0xFFFFFFFFu, acc.x, 20);
    float ry = acc.y + __shfl_down_sync(0xFFFFFFFFu, acc.y, 10) + __shfl_down_sync(0xFFFFFFFFu, acc.y, 20);
    float rz = acc.z + __shfl_down_sync(0xFFFFFFFFu, acc.z, 10) + __shfl_down_sync(0xFFFFFFFFu, acc.z, 20);
    float rw = acc.w + __shfl_down_sync(0xFFFFFFFFu, acc.w, 10) + __shfl_down_sync(0xFFFFFFFFu, acc.w, 20);

    float4 v = make_float4(-CUDART_INF_F, -CUDART_INF_F, -CUDART_INF_F, -CUDART_INF_F);
    if (lane < 10) {
        float d = rsqrtf((float)(deg + 1));
        float4 bb = ((const float4*)b2)[c];
        v.x = fmaf(d, rx, bb.x);
        v.y = fmaf(d, ry, bb.y);
        v.z = fmaf(d, rz, bb.z);
        v.w = fmaf(d, rw, bb.w);
    }
    float m = fmaxf(fmaxf(v.x, v.y), fmaxf(v.z, v.w));
#pragma unroll
    for (int o = 16; o; o >>= 1) m = fmaxf(m, __shfl_xor_sync(0xFFFFFFFFu, m, o));
    float s = 0.f;
    if (lane < 10)
        s = expf(v.x - m) + expf(v.y - m) + expf(v.z - m) + expf(v.w - m);
#pragma unroll
    for (int o = 16; o; o >>= 1) s += __shfl_xor_sync(0xFFFFFFFFu, s, o);
    float lse = m + logf(s);

    if (lane < 10) {
        float4 o4 = make_float4(v.x - lse, v.y - lse, v.z - lse, v.w - lse);
        ((float4*)out)[(unsigned)(node * 10 + c)] = o4;
    }
}

// ---------------- launch -----------------------------------------------------
extern "C" void kernel_launch(void* const* d_in, const int* in_sizes, int n_in,
                              void* d_out, int out_size) {
    const float* x  = (const float*)d_in[0];
    const int*   ei = (const int*)d_in[1];     // [2, NE] row-major
    const float* W1 = (const float*)d_in[2];
    const float* b1 = (const float*)d_in[3];
    const float* W2 = (const float*)d_in[4];
    const float* b2 = (const float*)d_in[5];
    float* out = (float*)d_out;
    const int* src = ei;
    const int* dst = ei + NE;

    void* cnt_ptr = nullptr;
    cudaGetSymbolAddress(&cnt_ptr, g_cnt);
    cudaMemsetAsync(cnt_ptr, 0, NN * sizeof(int));

    k_fill_gemm1<<<NBF + NBG, 256>>>(src, dst, x, W1);   // slot fill ∥ GEMM1
    k_agg1<<<(NN * 32 + 255) / 256, 256>>>(b1);
    k_gemm2<<<(NN + 63) / 64, 320>>>(W2);
    k_agg2<<<(NN * 32 + 255) / 256, 256>>>(b2, out);
}